// round 7
// baseline (speedup 1.0000x reference)
#include <cuda_runtime.h>
#include <cuda_bf16.h>
#include <math.h>

// Problem constants
#define BATCH 64
#define TT    1024
#define DIN   64
#define HID   128
#define G3    384   // 3*HID
#define D2    256   // 2*HID
#define MROWS (BATCH*TT)   // 65536

typedef unsigned long long ull;

// ---------------- f32x2 packed helpers (sm_103a FFMA2) ----------------------
__device__ __forceinline__ ull fma2(ull a, ull b, ull c) {
    ull d;
    asm("fma.rn.f32x2 %0, %1, %2, %3;" : "=l"(d) : "l"(a), "l"(b), "l"(c));
    return d;
}
__device__ __forceinline__ ull pack2(float lo, float hi) {
    ull d;
    asm("mov.b64 %0, {%1, %2};" : "=l"(d) : "f"(lo), "f"(hi));
    return d;
}
__device__ __forceinline__ float2 unpack2(ull v) {
    float2 r;
    asm("mov.b64 {%0, %1}, %2;" : "=f"(r.x), "=f"(r.y) : "l"(v));
    return r;
}
__device__ __forceinline__ float sigm(float x) {
    return 1.f / (1.f + __expf(-x));
}
__device__ __forceinline__ float ftanh(float x) {
    return __fmaf_rn(2.f, 1.f / (1.f + __expf(-2.f * x)), -1.f);
}

// ---------------- scratch (device globals; no allocation allowed) ----------
__device__ float g_xW[2][MROWS][G3];   // per-dir input projections (reused L0/L1)
__device__ float g_z0[MROWS][D2];      // layer-0 output [b*T+t][256]
__device__ float g_z1[MROWS][D2];      // layer-1 output

// ---------------- input projection GEMM: C = A @ W^T + bih (+bhh for r,z) --
// BM=128, BN=128, BK=16; 256 threads; 8x8 micro-tile via FFMA2.
// W duplicated (w,w) in smem at store time -> no per-kk pack movs.
// Thread (ty,tx): rows m0+ty*8 .. +7 (as 4 f32x2 pairs),
//                 cols n0 + 2*tx + d + 32*k   (d in {0,1}, k in 0..3)
__global__ __launch_bounds__(256)
void proj_gemm_kernel(const float* __restrict__ A0,
                      const float* __restrict__ Wf, const float* __restrict__ Wb,
                      const float* __restrict__ bf, const float* __restrict__ bb,
                      const float* __restrict__ bhf, const float* __restrict__ bhb,
                      int K, int layer)
{
    constexpr int BM = 128, BN = 128, BK = 16;
    __shared__ __align__(16) float As[BK][BM + 4];
    __shared__ __align__(16) ull   Wd[BK][BN + 2];

    const int dir = blockIdx.z;
    const float* __restrict__ A    = layer ? (const float*)g_z0 : A0;
    const float* __restrict__ Wp   = dir ? Wb : Wf;
    const float* __restrict__ bias = dir ? bb : bf;
    const float* __restrict__ bhh  = dir ? bhb : bhf;

    const int m0 = blockIdx.x * BM;
    const int n0 = blockIdx.y * BN;

    const int tid  = threadIdx.x;
    const int lrow = tid >> 1;            // 0..127 (row for loads)
    const int kq   = (tid & 1) * 8;       // 0 or 8
    const int tx   = tid & 15;            // N micro
    const int ty   = tid >> 4;            // M micro

    ull acc2[4][8];                       // [m_pair][j = 2k+d]
    #pragma unroll
    for (int i = 0; i < 4; ++i)
        #pragma unroll
        for (int j = 0; j < 8; ++j) acc2[i][j] = 0ull;

    for (int k0 = 0; k0 < K; k0 += BK) {
        // load A tile (128 x 16) transposed into As
        {
            const float* p = A + (size_t)(m0 + lrow) * K + k0 + kq;
            float4 v0 = *(const float4*)p;
            float4 v1 = *(const float4*)(p + 4);
            As[kq + 0][lrow] = v0.x; As[kq + 1][lrow] = v0.y;
            As[kq + 2][lrow] = v0.z; As[kq + 3][lrow] = v0.w;
            As[kq + 4][lrow] = v1.x; As[kq + 5][lrow] = v1.y;
            As[kq + 6][lrow] = v1.z; As[kq + 7][lrow] = v1.w;
        }
        // load W tile (128 x 16) transposed + duplicated into Wd
        {
            const float* p = Wp + (size_t)(n0 + lrow) * K + k0 + kq;
            float4 v0 = *(const float4*)p;
            float4 v1 = *(const float4*)(p + 4);
            Wd[kq + 0][lrow] = pack2(v0.x, v0.x);
            Wd[kq + 1][lrow] = pack2(v0.y, v0.y);
            Wd[kq + 2][lrow] = pack2(v0.z, v0.z);
            Wd[kq + 3][lrow] = pack2(v0.w, v0.w);
            Wd[kq + 4][lrow] = pack2(v1.x, v1.x);
            Wd[kq + 5][lrow] = pack2(v1.y, v1.y);
            Wd[kq + 6][lrow] = pack2(v1.z, v1.z);
            Wd[kq + 7][lrow] = pack2(v1.w, v1.w);
        }
        __syncthreads();

        #pragma unroll
        for (int kk = 0; kk < BK; ++kk) {
            ulonglong2 a01 = *(const ulonglong2*)&As[kk][ty * 8];       // rows (0,1),(2,3)
            ulonglong2 a23 = *(const ulonglong2*)&As[kk][ty * 8 + 4];   // rows (4,5),(6,7)
            ull am[4] = {a01.x, a01.y, a23.x, a23.y};
            #pragma unroll
            for (int k = 0; k < 4; ++k) {
                ulonglong2 wv = *(const ulonglong2*)&Wd[kk][2 * tx + 32 * k];
                #pragma unroll
                for (int i = 0; i < 4; ++i) {
                    acc2[i][2 * k]     = fma2(am[i], wv.x, acc2[i][2 * k]);
                    acc2[i][2 * k + 1] = fma2(am[i], wv.y, acc2[i][2 * k + 1]);
                }
            }
        }
        __syncthreads();
    }

    // epilogue: bias (+bhh fold for r,z tiles), write float2 per (row, k)
    float* Cout = &g_xW[dir][0][0];
    const bool fold = (n0 < 2 * HID);
    float2 bz[4];
    #pragma unroll
    for (int k = 0; k < 4; ++k) {
        int c = n0 + 2 * tx + 32 * k;
        bz[k].x = bias[c]     + (fold ? bhh[c]     : 0.f);
        bz[k].y = bias[c + 1] + (fold ? bhh[c + 1] : 0.f);
    }
    #pragma unroll
    for (int i = 0; i < 4; ++i) {
        #pragma unroll
        for (int pp = 0; pp < 2; ++pp) {
            float* Crow = Cout + (size_t)(m0 + ty * 8 + 2 * i + pp) * G3 + n0 + 2 * tx;
            #pragma unroll
            for (int k = 0; k < 4; ++k) {
                float2 cd = unpack2(acc2[i][2 * k]);
                float2 ce = unpack2(acc2[i][2 * k + 1]);
                float2 o;
                o.x = (pp ? cd.y : cd.x) + bz[k].x;
                o.y = (pp ? ce.y : ce.x) + bz[k].y;
                *(float2*)(Crow + 32 * k) = o;
            }
        }
    }
}

// ---------------- GRU recurrence (R5 structure — best known) ---------------
// 384 threads = rows (r:0-127, z:128-255, n:256-383).
// Each thread: 1 uniform gi load (own row), full Whh row in regs, pure dot.
// r,z threads apply their sigmoid BEFORE bar1 (overlapped, 8 warps) -> STS 256.
// n threads (warps 8-11, one per SMSP) do the short tail: tanh + blend.
__global__ __launch_bounds__(384, 1)
void gru_scan_kernel(const float* __restrict__ whh_f, const float* __restrict__ whh_b,
                     const float* __restrict__ bhh_f, const float* __restrict__ bhh_b,
                     int layer)
{
    const int b   = blockIdx.x >> 1;
    const int dir = blockIdx.x & 1;
    const int j   = threadIdx.x;                 // 0..383 = gate row

    const float* __restrict__ whh = dir ? whh_b : whh_f;
    const float* __restrict__ bhh = dir ? bhh_b : bhh_f;

    __shared__ __align__(16) float h_s[HID];
    __shared__ float rz_s[2 * HID];

    // load Whh row j into 64 packed f32x2 registers
    ull w2[64];
    #pragma unroll
    for (int i = 0; i < 64; i += 2) {
        ulonglong2 v = *(const ulonglong2*)(whh + (size_t)j * HID + 2 * i);
        w2[i] = v.x; w2[i + 1] = v.y;
    }
    const bool is_n = (j >= 2 * HID);
    const int  o    = j - 2 * HID;               // output index for n-threads
    const float bj  = is_n ? bhh[j] : 0.f;       // bhh_n stays inside r*(.)
    float hreg = 0.f;
    if (j < HID) h_s[j] = 0.f;

    const float* __restrict__ gi = &g_xW[dir][(size_t)b * TT][0];
    float* __restrict__ zout = (layer ? &g_z1[(size_t)b * TT][0]
                                      : &g_z0[(size_t)b * TT][0]) + dir * HID;

    // preload own-row gi for the first step
    const int t0 = dir ? (TT - 1) : 0;
    float gi_v = __ldcs(gi + (size_t)t0 * G3 + j);
    __syncthreads();

    for (int t = 0; t < TT; ++t) {
        const int tt = dir ? (TT - 1 - t) : t;

        // prefetch NEXT step's gi (covered by a full step of work)
        float pre = 0.f;
        if (t + 1 < TT) {
            const int tn = dir ? (TT - 2 - t) : (t + 1);
            pre = __ldcs(gi + (size_t)tn * G3 + j);
        }

        // gh = Whh[j,:] . h   (pure dot; explicit LDS staging)
        ull a0 = 0ull, a1 = 0ull;
        const ull* h2 = (const ull*)h_s;
        #pragma unroll
        for (int i = 0; i < 64; i += 8) {
            ulonglong2 hv0 = *(const ulonglong2*)(h2 + i);
            ulonglong2 hv1 = *(const ulonglong2*)(h2 + i + 2);
            ulonglong2 hv2 = *(const ulonglong2*)(h2 + i + 4);
            ulonglong2 hv3 = *(const ulonglong2*)(h2 + i + 6);
            a0 = fma2(w2[i],     hv0.x, a0);
            a1 = fma2(w2[i + 1], hv0.y, a1);
            a0 = fma2(w2[i + 2], hv1.x, a0);
            a1 = fma2(w2[i + 3], hv1.y, a1);
            a0 = fma2(w2[i + 4], hv2.x, a0);
            a1 = fma2(w2[i + 5], hv2.y, a1);
            a0 = fma2(w2[i + 6], hv3.x, a0);
            a1 = fma2(w2[i + 7], hv3.y, a1);
        }
        float2 s0 = unpack2(a0), s1 = unpack2(a1);
        float gh = (s0.x + s0.y) + (s1.x + s1.y);

        // r,z threads: apply sigmoid here (parallel across 8 warps), publish
        if (!is_n) rz_s[j] = sigm(gi_v + gh);
        __syncthreads();

        // n threads: short tail = tanh + blend
        if (is_n) {
            float r  = rz_s[o];
            float zg = rz_s[HID + o];
            float n  = ftanh(gi_v + r * (gh + bj));
            hreg = (1.f - zg) * n + zg * hreg;
            h_s[o] = hreg;
            zout[(size_t)tt * D2 + o] = hreg;
        }
        gi_v = pre;
        __syncthreads();
    }
}

// ---------------- attention pooling + heads --------------------------------
__global__ __launch_bounds__(256)
void attn_head_kernel(const float* __restrict__ attn_w, const float* __restrict__ attn_b,
                      const float* __restrict__ motor_w, const float* __restrict__ motor_b,
                      const float* __restrict__ state_w, const float* __restrict__ state_b,
                      const int* __restrict__ motor_k, float* __restrict__ out)
{
    const int b = blockIdx.x;
    const int tid = threadIdx.x;       // 256 threads
    const int warp = tid >> 5, lane = tid & 31;

    __shared__ float sw[D2];
    __shared__ float sc[TT];
    __shared__ float red[256];
    __shared__ float pooled[D2];

    sw[tid] = attn_w[tid];
    __syncthreads();

    const float* __restrict__ zb = &g_z1[(size_t)b * TT][0];
    const float ab = attn_b[0];

    for (int t = warp; t < TT; t += 8) {
        const float* zt = zb + (size_t)t * D2;
        float s = 0.f;
        #pragma unroll
        for (int d = lane; d < D2; d += 32) s += zt[d] * sw[d];
        #pragma unroll
        for (int o = 16; o; o >>= 1) s += __shfl_xor_sync(0xffffffffu, s, o);
        if (lane == 0) sc[t] = s + ab;
    }
    __syncthreads();

    float m = -INFINITY;
    for (int t = tid; t < TT; t += 256) m = fmaxf(m, sc[t]);
    red[tid] = m; __syncthreads();
    for (int s = 128; s; s >>= 1) {
        if (tid < s) red[tid] = fmaxf(red[tid], red[tid + s]);
        __syncthreads();
    }
    m = red[0]; __syncthreads();

    float sum = 0.f;
    for (int t = tid; t < TT; t += 256) {
        float e = __expf(sc[t] - m);
        sc[t] = e;
        sum += e;
    }
    red[tid] = sum; __syncthreads();
    for (int s = 128; s; s >>= 1) {
        if (tid < s) red[tid] += red[tid + s];
        __syncthreads();
    }
    const float inv = 1.f / red[0];
    __syncthreads();

    float acc = 0.f;
    #pragma unroll 8
    for (int t = 0; t < TT; ++t) acc += sc[t] * zb[(size_t)t * D2 + tid];
    pooled[tid] = acc * inv;
    __syncthreads();

    if (warp < 7) {
        const float* wv;
        float bv;
        int mk = motor_k[b];
        if (warp < 5) { wv = motor_w + warp * D2;              bv = motor_b[warp]; }
        else          { int c = warp - 5;
                        wv = state_w + (size_t)(mk * 2 + c) * D2;
                        bv = state_b[mk * 2 + c]; }
        float s = 0.f;
        #pragma unroll
        for (int d = lane; d < D2; d += 32) s += pooled[d] * wv[d];
        #pragma unroll
        for (int o = 16; o; o >>= 1) s += __shfl_xor_sync(0xffffffffu, s, o);
        if (lane == 0) {
            if (warp < 5) out[b * 5 + warp] = s + bv;
            else          out[BATCH * 5 + b * 2 + (warp - 5)] = s + bv;
        }
    }
}

// ---------------- launch ----------------------------------------------------
extern "C" void kernel_launch(void* const* d_in, const int* in_sizes, int n_in,
                              void* d_out, int out_size)
{
    const float* x        = (const float*)d_in[0];
    const int*   motor_k  = (const int*)  d_in[1];
    const float* wih_l0f  = (const float*)d_in[2];
    const float* whh_l0f  = (const float*)d_in[3];
    const float* bih_l0f  = (const float*)d_in[4];
    const float* bhh_l0f  = (const float*)d_in[5];
    const float* wih_l0b  = (const float*)d_in[6];
    const float* whh_l0b  = (const float*)d_in[7];
    const float* bih_l0b  = (const float*)d_in[8];
    const float* bhh_l0b  = (const float*)d_in[9];
    const float* wih_l1f  = (const float*)d_in[10];
    const float* whh_l1f  = (const float*)d_in[11];
    const float* bih_l1f  = (const float*)d_in[12];
    const float* bhh_l1f  = (const float*)d_in[13];
    const float* wih_l1b  = (const float*)d_in[14];
    const float* whh_l1b  = (const float*)d_in[15];
    const float* bih_l1b  = (const float*)d_in[16];
    const float* bhh_l1b  = (const float*)d_in[17];
    const float* attn_w   = (const float*)d_in[18];
    const float* attn_b   = (const float*)d_in[19];
    const float* motor_w  = (const float*)d_in[20];
    const float* motor_b  = (const float*)d_in[21];
    const float* state_w  = (const float*)d_in[22];
    const float* state_b  = (const float*)d_in[23];
    float* out = (float*)d_out;

    dim3 gproj(MROWS / 128, G3 / 128, 2);   // 512 x 3 x 2

    // layer 0
    proj_gemm_kernel<<<gproj, 256>>>(x, wih_l0f, wih_l0b, bih_l0f, bih_l0b,
                                     bhh_l0f, bhh_l0b, DIN, 0);
    gru_scan_kernel<<<BATCH * 2, 384>>>(whh_l0f, whh_l0b, bhh_l0f, bhh_l0b, 0);
    // layer 1
    proj_gemm_kernel<<<gproj, 256>>>(nullptr, wih_l1f, wih_l1b, bih_l1f, bih_l1b,
                                     bhh_l1f, bhh_l1b, D2, 1);
    gru_scan_kernel<<<BATCH * 2, 384>>>(whh_l1f, whh_l1b, bhh_l1f, bhh_l1b, 1);
    // pooling + heads
    attn_head_kernel<<<BATCH, 256>>>(attn_w, attn_b, motor_w, motor_b,
                                     state_w, state_b, motor_k, out);
}

// round 8
// speedup vs baseline: 1.1091x; 1.1091x over previous
#include <cuda_runtime.h>
#include <cuda_bf16.h>
#include <math.h>

// Problem constants
#define BATCH 64
#define TT    1024
#define DIN   64
#define HID   128
#define G3    384   // 3*HID
#define D2    256   // 2*HID
#define MROWS (BATCH*TT)   // 65536

typedef unsigned long long ull;

// ---------------- f32x2 packed helpers (sm_103a FFMA2) ----------------------
__device__ __forceinline__ ull fma2(ull a, ull b, ull c) {
    ull d;
    asm("fma.rn.f32x2 %0, %1, %2, %3;" : "=l"(d) : "l"(a), "l"(b), "l"(c));
    return d;
}
__device__ __forceinline__ ull pack2(float lo, float hi) {
    ull d;
    asm("mov.b64 %0, {%1, %2};" : "=l"(d) : "f"(lo), "f"(hi));
    return d;
}
__device__ __forceinline__ float2 unpack2(ull v) {
    float2 r;
    asm("mov.b64 {%0, %1}, %2;" : "=f"(r.x), "=f"(r.y) : "l"(v));
    return r;
}
__device__ __forceinline__ float sigm(float x) {
    return 1.f / (1.f + __expf(-x));
}
__device__ __forceinline__ float ftanh(float x) {
    return __fmaf_rn(2.f, 1.f / (1.f + __expf(-2.f * x)), -1.f);
}

// ---------------- scratch (device globals; no allocation allowed) ----------
__device__ float g_xW[2][MROWS][G3];   // per-dir input projections (reused L0/L1)
__device__ float g_z0[MROWS][D2];      // layer-0 output [b*T+t][256]
__device__ float g_z1[MROWS][D2];      // layer-1 output

// ---------------- input projection GEMM: C = A @ W^T + bih (+bhh for r,z) --
// R5 shape (BM=128, BN=64, BK=16, 256 thr, 8x4 micro via FFMA2) plus
// double-buffered smem: LDG for tile i+1 register-staged under compute of i,
// one barrier per k-iteration.
__global__ __launch_bounds__(256)
void proj_gemm_kernel(const float* __restrict__ A0,
                      const float* __restrict__ Wf, const float* __restrict__ Wb,
                      const float* __restrict__ bf, const float* __restrict__ bb,
                      const float* __restrict__ bhf, const float* __restrict__ bhb,
                      int K, int layer)
{
    constexpr int BM = 128, BN = 64, BK = 16;
    __shared__ __align__(16) float As[2][BK][BM + 4];
    __shared__ __align__(16) float Ws[2][BK][BN + 4];

    const int dir = blockIdx.z;
    const float* __restrict__ A    = layer ? (const float*)g_z0 : A0;
    const float* __restrict__ Wp   = dir ? Wb : Wf;
    const float* __restrict__ bias = dir ? bb : bf;
    const float* __restrict__ bhh  = dir ? bhb : bhf;

    const int m0 = blockIdx.x * BM;
    const int n0 = blockIdx.y * BN;

    const int tid  = threadIdx.x;
    const int arow = tid >> 2;           // 0..63
    const int kq   = (tid & 3) * 4;      // 0,4,8,12
    const int tx   = tid & 15;           // N micro (4)
    const int ty   = tid >> 4;           // M micro (8 rows = 4 f32x2 pairs)

    const float* pA = A  + (size_t)(m0 + arow) * K + kq;
    const float* pW = Wp + (size_t)(n0 + arow) * K + kq;

    ull acc2[4][4];
    #pragma unroll
    for (int i = 0; i < 4; ++i)
        #pragma unroll
        for (int j = 0; j < 4; ++j) acc2[i][j] = 0ull;

    // prologue: load tile 0 to regs, stage into buffer 0
    float4 av0 = *(const float4*)pA;
    float4 av1 = *(const float4*)(pA + (size_t)64 * K);
    float4 wv  = *(const float4*)pW;
    {
        As[0][kq + 0][arow] = av0.x; As[0][kq + 1][arow] = av0.y;
        As[0][kq + 2][arow] = av0.z; As[0][kq + 3][arow] = av0.w;
        As[0][kq + 0][arow + 64] = av1.x; As[0][kq + 1][arow + 64] = av1.y;
        As[0][kq + 2][arow + 64] = av1.z; As[0][kq + 3][arow + 64] = av1.w;
        Ws[0][kq + 0][arow] = wv.x; Ws[0][kq + 1][arow] = wv.y;
        Ws[0][kq + 2][arow] = wv.z; Ws[0][kq + 3][arow] = wv.w;
    }
    __syncthreads();

    const int niter = K / BK;
    for (int it = 0; it < niter; ++it) {
        const int cur = it & 1;

        // prefetch next tile to registers (hidden under compute below)
        if (it + 1 < niter) {
            const int k0 = (it + 1) * BK;
            av0 = *(const float4*)(pA + k0);
            av1 = *(const float4*)(pA + (size_t)64 * K + k0);
            wv  = *(const float4*)(pW + k0);
        }

        #pragma unroll
        for (int kk = 0; kk < BK; ++kk) {
            ulonglong2 a01 = *(const ulonglong2*)&As[cur][kk][ty * 8];
            ulonglong2 a23 = *(const ulonglong2*)&As[cur][kk][ty * 8 + 4];
            float4 w4 = *(const float4*)&Ws[cur][kk][tx * 4];
            ull am[4] = {a01.x, a01.y, a23.x, a23.y};
            ull wp[4] = {pack2(w4.x, w4.x), pack2(w4.y, w4.y),
                         pack2(w4.z, w4.z), pack2(w4.w, w4.w)};
            #pragma unroll
            for (int i = 0; i < 4; ++i)
                #pragma unroll
                for (int j = 0; j < 4; ++j)
                    acc2[i][j] = fma2(am[i], wp[j], acc2[i][j]);
        }

        // stage next tile into the other buffer
        if (it + 1 < niter) {
            const int nxt = (it + 1) & 1;
            As[nxt][kq + 0][arow] = av0.x; As[nxt][kq + 1][arow] = av0.y;
            As[nxt][kq + 2][arow] = av0.z; As[nxt][kq + 3][arow] = av0.w;
            As[nxt][kq + 0][arow + 64] = av1.x; As[nxt][kq + 1][arow + 64] = av1.y;
            As[nxt][kq + 2][arow + 64] = av1.z; As[nxt][kq + 3][arow + 64] = av1.w;
            Ws[nxt][kq + 0][arow] = wv.x; Ws[nxt][kq + 1][arow] = wv.y;
            Ws[nxt][kq + 2][arow] = wv.z; Ws[nxt][kq + 3][arow] = wv.w;
        }
        __syncthreads();
    }

    float* Cout = &g_xW[dir][0][0];
    float4 b4 = *(const float4*)(bias + n0 + tx * 4);
    if (n0 < 2 * HID) {   // fold bhh into r,z gate biases (n-gate keeps bhh apart)
        float4 bh4 = *(const float4*)(bhh + n0 + tx * 4);
        b4.x += bh4.x; b4.y += bh4.y; b4.z += bh4.z; b4.w += bh4.w;
    }
    float* Crow = Cout + (size_t)(m0 + ty * 8) * G3 + n0 + tx * 4;
    #pragma unroll
    for (int i = 0; i < 4; ++i) {
        float2 c0 = unpack2(acc2[i][0]);
        float2 c1 = unpack2(acc2[i][1]);
        float2 c2 = unpack2(acc2[i][2]);
        float2 c3 = unpack2(acc2[i][3]);
        float4 lo = {c0.x + b4.x, c1.x + b4.y, c2.x + b4.z, c3.x + b4.w};
        float4 hi = {c0.y + b4.x, c1.y + b4.y, c2.y + b4.z, c3.y + b4.w};
        *(float4*)(Crow + (size_t)(2 * i)     * G3) = lo;
        *(float4*)(Crow + (size_t)(2 * i + 1) * G3) = hi;
    }
}

// ---------------- GRU recurrence (R5 structure — best known) ---------------
__global__ __launch_bounds__(384, 1)
void gru_scan_kernel(const float* __restrict__ whh_f, const float* __restrict__ whh_b,
                     const float* __restrict__ bhh_f, const float* __restrict__ bhh_b,
                     int layer)
{
    const int b   = blockIdx.x >> 1;
    const int dir = blockIdx.x & 1;
    const int j   = threadIdx.x;                 // 0..383 = gate row

    const float* __restrict__ whh = dir ? whh_b : whh_f;
    const float* __restrict__ bhh = dir ? bhh_b : bhh_f;

    __shared__ __align__(16) float h_s[HID];
    __shared__ float rz_s[2 * HID];

    // load Whh row j into 64 packed f32x2 registers
    ull w2[64];
    #pragma unroll
    for (int i = 0; i < 64; i += 2) {
        ulonglong2 v = *(const ulonglong2*)(whh + (size_t)j * HID + 2 * i);
        w2[i] = v.x; w2[i + 1] = v.y;
    }
    const bool is_n = (j >= 2 * HID);
    const int  o    = j - 2 * HID;               // output index for n-threads
    const float bj  = is_n ? bhh[j] : 0.f;       // bhh_n stays inside r*(.)
    float hreg = 0.f;
    if (j < HID) h_s[j] = 0.f;

    const float* __restrict__ gi = &g_xW[dir][(size_t)b * TT][0];
    float* __restrict__ zout = (layer ? &g_z1[(size_t)b * TT][0]
                                      : &g_z0[(size_t)b * TT][0]) + dir * HID;

    // preload own-row gi for the first step
    const int t0 = dir ? (TT - 1) : 0;
    float gi_v = __ldcs(gi + (size_t)t0 * G3 + j);
    __syncthreads();

    for (int t = 0; t < TT; ++t) {
        const int tt = dir ? (TT - 1 - t) : t;

        // prefetch NEXT step's gi (covered by a full step of work)
        float pre = 0.f;
        if (t + 1 < TT) {
            const int tn = dir ? (TT - 2 - t) : (t + 1);
            pre = __ldcs(gi + (size_t)tn * G3 + j);
        }

        // gh = Whh[j,:] . h   (pure dot; explicit LDS staging)
        ull a0 = 0ull, a1 = 0ull;
        const ull* h2 = (const ull*)h_s;
        #pragma unroll
        for (int i = 0; i < 64; i += 8) {
            ulonglong2 hv0 = *(const ulonglong2*)(h2 + i);
            ulonglong2 hv1 = *(const ulonglong2*)(h2 + i + 2);
            ulonglong2 hv2 = *(const ulonglong2*)(h2 + i + 4);
            ulonglong2 hv3 = *(const ulonglong2*)(h2 + i + 6);
            a0 = fma2(w2[i],     hv0.x, a0);
            a1 = fma2(w2[i + 1], hv0.y, a1);
            a0 = fma2(w2[i + 2], hv1.x, a0);
            a1 = fma2(w2[i + 3], hv1.y, a1);
            a0 = fma2(w2[i + 4], hv2.x, a0);
            a1 = fma2(w2[i + 5], hv2.y, a1);
            a0 = fma2(w2[i + 6], hv3.x, a0);
            a1 = fma2(w2[i + 7], hv3.y, a1);
        }
        float2 s0 = unpack2(a0), s1 = unpack2(a1);
        float gh = (s0.x + s0.y) + (s1.x + s1.y);

        // r,z threads: apply sigmoid here (parallel across 8 warps), publish
        if (!is_n) rz_s[j] = sigm(gi_v + gh);
        __syncthreads();

        // n threads: short tail = tanh + blend
        if (is_n) {
            float r  = rz_s[o];
            float zg = rz_s[HID + o];
            float n  = ftanh(gi_v + r * (gh + bj));
            hreg = (1.f - zg) * n + zg * hreg;
            h_s[o] = hreg;
            zout[(size_t)tt * D2 + o] = hreg;
        }
        gi_v = pre;
        __syncthreads();
    }
}

// ---------------- attention pooling + heads --------------------------------
__global__ __launch_bounds__(256)
void attn_head_kernel(const float* __restrict__ attn_w, const float* __restrict__ attn_b,
                      const float* __restrict__ motor_w, const float* __restrict__ motor_b,
                      const float* __restrict__ state_w, const float* __restrict__ state_b,
                      const int* __restrict__ motor_k, float* __restrict__ out)
{
    const int b = blockIdx.x;
    const int tid = threadIdx.x;       // 256 threads
    const int warp = tid >> 5, lane = tid & 31;

    __shared__ float sw[D2];
    __shared__ float sc[TT];
    __shared__ float red[256];
    __shared__ float pooled[D2];

    sw[tid] = attn_w[tid];
    __syncthreads();

    const float* __restrict__ zb = &g_z1[(size_t)b * TT][0];
    const float ab = attn_b[0];

    for (int t = warp; t < TT; t += 8) {
        const float* zt = zb + (size_t)t * D2;
        float s = 0.f;
        #pragma unroll
        for (int d = lane; d < D2; d += 32) s += zt[d] * sw[d];
        #pragma unroll
        for (int o = 16; o; o >>= 1) s += __shfl_xor_sync(0xffffffffu, s, o);
        if (lane == 0) sc[t] = s + ab;
    }
    __syncthreads();

    float m = -INFINITY;
    for (int t = tid; t < TT; t += 256) m = fmaxf(m, sc[t]);
    red[tid] = m; __syncthreads();
    for (int s = 128; s; s >>= 1) {
        if (tid < s) red[tid] = fmaxf(red[tid], red[tid + s]);
        __syncthreads();
    }
    m = red[0]; __syncthreads();

    float sum = 0.f;
    for (int t = tid; t < TT; t += 256) {
        float e = __expf(sc[t] - m);
        sc[t] = e;
        sum += e;
    }
    red[tid] = sum; __syncthreads();
    for (int s = 128; s; s >>= 1) {
        if (tid < s) red[tid] += red[tid + s];
        __syncthreads();
    }
    const float inv = 1.f / red[0];
    __syncthreads();

    float acc = 0.f;
    #pragma unroll 8
    for (int t = 0; t < TT; ++t) acc += sc[t] * zb[(size_t)t * D2 + tid];
    pooled[tid] = acc * inv;
    __syncthreads();

    if (warp < 7) {
        const float* wv;
        float bv;
        int mk = motor_k[b];
        if (warp < 5) { wv = motor_w + warp * D2;              bv = motor_b[warp]; }
        else          { int c = warp - 5;
                        wv = state_w + (size_t)(mk * 2 + c) * D2;
                        bv = state_b[mk * 2 + c]; }
        float s = 0.f;
        #pragma unroll
        for (int d = lane; d < D2; d += 32) s += pooled[d] * wv[d];
        #pragma unroll
        for (int o = 16; o; o >>= 1) s += __shfl_xor_sync(0xffffffffu, s, o);
        if (lane == 0) {
            if (warp < 5) out[b * 5 + warp] = s + bv;
            else          out[BATCH * 5 + b * 2 + (warp - 5)] = s + bv;
        }
    }
}

// ---------------- launch ----------------------------------------------------
extern "C" void kernel_launch(void* const* d_in, const int* in_sizes, int n_in,
                              void* d_out, int out_size)
{
    const float* x        = (const float*)d_in[0];
    const int*   motor_k  = (const int*)  d_in[1];
    const float* wih_l0f  = (const float*)d_in[2];
    const float* whh_l0f  = (const float*)d_in[3];
    const float* bih_l0f  = (const float*)d_in[4];
    const float* bhh_l0f  = (const float*)d_in[5];
    const float* wih_l0b  = (const float*)d_in[6];
    const float* whh_l0b  = (const float*)d_in[7];
    const float* bih_l0b  = (const float*)d_in[8];
    const float* bhh_l0b  = (const float*)d_in[9];
    const float* wih_l1f  = (const float*)d_in[10];
    const float* whh_l1f  = (const float*)d_in[11];
    const float* bih_l1f  = (const float*)d_in[12];
    const float* bhh_l1f  = (const float*)d_in[13];
    const float* wih_l1b  = (const float*)d_in[14];
    const float* whh_l1b  = (const float*)d_in[15];
    const float* bih_l1b  = (const float*)d_in[16];
    const float* bhh_l1b  = (const float*)d_in[17];
    const float* attn_w   = (const float*)d_in[18];
    const float* attn_b   = (const float*)d_in[19];
    const float* motor_w  = (const float*)d_in[20];
    const float* motor_b  = (const float*)d_in[21];
    const float* state_w  = (const float*)d_in[22];
    const float* state_b  = (const float*)d_in[23];
    float* out = (float*)d_out;

    dim3 gproj(MROWS / 128, G3 / 64, 2);

    // layer 0
    proj_gemm_kernel<<<gproj, 256>>>(x, wih_l0f, wih_l0b, bih_l0f, bih_l0b,
                                     bhh_l0f, bhh_l0b, DIN, 0);
    gru_scan_kernel<<<BATCH * 2, 384>>>(whh_l0f, whh_l0b, bhh_l0f, bhh_l0b, 0);
    // layer 1
    proj_gemm_kernel<<<gproj, 256>>>(nullptr, wih_l1f, wih_l1b, bih_l1f, bih_l1b,
                                     bhh_l1f, bhh_l1b, D2, 1);
    gru_scan_kernel<<<BATCH * 2, 384>>>(whh_l1f, whh_l1b, bhh_l1f, bhh_l1b, 1);
    // pooling + heads
    attn_head_kernel<<<BATCH, 256>>>(attn_w, attn_b, motor_w, motor_b,
                                     state_w, state_b, motor_k, out);
}

// round 10
// speedup vs baseline: 1.2088x; 1.0899x over previous
#include <cuda_runtime.h>
#include <cuda_bf16.h>
#include <math.h>
#include <stdint.h>

// Problem constants
#define BATCH 64
#define TT    1024
#define DIN   64
#define HID   128
#define G3    384   // 3*HID
#define D2    256   // 2*HID
#define MROWS (BATCH*TT)   // 65536

typedef unsigned long long ull;

// ---------------- f32x2 packed helpers (sm_103a FFMA2) ----------------------
__device__ __forceinline__ ull fma2(ull a, ull b, ull c) {
    ull d;
    asm("fma.rn.f32x2 %0, %1, %2, %3;" : "=l"(d) : "l"(a), "l"(b), "l"(c));
    return d;
}
__device__ __forceinline__ float2 unpack2(ull v) {
    float2 r;
    asm("mov.b64 {%0, %1}, %2;" : "=f"(r.x), "=f"(r.y) : "l"(v));
    return r;
}
__device__ __forceinline__ float sigm(float x) {
    return 1.f / (1.f + __expf(-x));
}
__device__ __forceinline__ float ftanh(float x) {
    return __fmaf_rn(2.f, 1.f / (1.f + __expf(-2.f * x)), -1.f);
}

// ---------------- bf16 HMMA (m16n8k16) --------------------------------------
__device__ __forceinline__ void mma_bf16(float* c,
                                         uint32_t a0, uint32_t a1, uint32_t a2, uint32_t a3,
                                         uint32_t b0, uint32_t b1) {
    asm volatile(
        "mma.sync.aligned.m16n8k16.row.col.f32.bf16.bf16.f32 "
        "{%0,%1,%2,%3}, {%4,%5,%6,%7}, {%8,%9}, {%0,%1,%2,%3};"
        : "+f"(c[0]), "+f"(c[1]), "+f"(c[2]), "+f"(c[3])
        : "r"(a0), "r"(a1), "r"(a2), "r"(a3), "r"(b0), "r"(b1));
}

// ---------------- scratch (device globals; no allocation allowed) ----------
__device__ float g_xW[2][MROWS][G3];          // input projections per dir
__device__ float g_z1[MROWS][D2];             // layer-1 output (fp32 for attn)
__device__ __nv_bfloat16 g_xh[MROWS * DIN],  g_xl[MROWS * DIN];
__device__ __nv_bfloat16 g_z0h[MROWS * D2],  g_z0l[MROWS * D2];
__device__ __nv_bfloat16 g_w0h[2][G3 * DIN], g_w0l[2][G3 * DIN];
__device__ __nv_bfloat16 g_w1h[2][G3 * D2],  g_w1l[2][G3 * D2];

// ---------------- fp32 -> bf16 (hi, lo) split conversion -------------------
__global__ __launch_bounds__(256)
void convert_kernel(const float* __restrict__ src, int which, int n)
{
    __nv_bfloat16 *hi, *lo;
    switch (which) {
        case 0: hi = g_xh;      lo = g_xl;      break;
        case 1: hi = g_w0h[0];  lo = g_w0l[0];  break;
        case 2: hi = g_w0h[1];  lo = g_w0l[1];  break;
        case 3: hi = g_w1h[0];  lo = g_w1l[0];  break;
        default: hi = g_w1h[1]; lo = g_w1l[1];  break;
    }
    for (int i = blockIdx.x * 256 + threadIdx.x; i < n; i += gridDim.x * 256) {
        float v = src[i];
        __nv_bfloat16 h = __float2bfloat16(v);
        hi[i] = h;
        lo[i] = __float2bfloat16(v - __bfloat162float(h));
    }
}

// ---------------- HMMA projection GEMM --------------------------------------
// C[m][n] = sum_k A[m][k]*W[n][k] + bias, 3-plane bf16 split.
// BM=128, BN=128, BK=32; 256 thr = 8 warps (4 m-rows x 2 n-cols),
// warp = 32(m) x 64(n) = 2 m-tiles(16) x 8 n-tiles(8), m16n8k16 fragments.
// smem rows padded to 40 bf16 -> conflict-free 32-bit fragment loads.
#define LDP 40
__global__ __launch_bounds__(256, 1)
void mma_proj_kernel(const float* __restrict__ bf,  const float* __restrict__ bb,
                     const float* __restrict__ bhf, const float* __restrict__ bhb,
                     int K, int layer)
{
    __shared__ __align__(16) __nv_bfloat16 sAh[128][LDP];
    __shared__ __align__(16) __nv_bfloat16 sAl[128][LDP];
    __shared__ __align__(16) __nv_bfloat16 sWh[128][LDP];
    __shared__ __align__(16) __nv_bfloat16 sWl[128][LDP];
    __shared__ float sBias[128];

    const int tid  = threadIdx.x;
    const int wid  = tid >> 5;
    const int lane = tid & 31;
    const int g    = lane >> 2;          // 0..7
    const int tig  = lane & 3;           // 0..3
    const int wr   = wid >> 1;           // 0..3  (m offset wr*32)
    const int wc   = wid & 1;            // 0..1  (n offset wc*64)
    const int m0   = blockIdx.x * 128;
    const int n0   = blockIdx.y * 128;
    const int dir  = blockIdx.z;

    const __nv_bfloat16* __restrict__ Ah = layer ? g_z0h : g_xh;
    const __nv_bfloat16* __restrict__ Al = layer ? g_z0l : g_xl;
    const __nv_bfloat16* __restrict__ Wh = layer ? g_w1h[dir] : g_w0h[dir];
    const __nv_bfloat16* __restrict__ Wl = layer ? g_w1l[dir] : g_w0l[dir];
    const float* __restrict__ bias = dir ? bb : bf;
    const float* __restrict__ bhh  = dir ? bhb : bhf;

    // bias (+bhh fold for r,z gate columns: global col < 256)
    if (tid < 128) {
        int c = n0 + tid;
        sBias[tid] = bias[c] + (c < 2 * HID ? bhh[c] : 0.f);
    }

    // load indices: each thread moves 2 uint4 per plane per tile
    // A tile: 128 rows x 32 cols = 512 uint4 -> i = tid, tid+256
    // W tile: same shape
    const int lr0 = tid >> 1;                 // 0..127
    const int lc0 = (tid & 1) * 16;           // 0 or 16 (element col)
    // thread handles (lr0, lc0..lc0+7) and (lr0, lc0+8..+15)

    float acc[2][8][4];
    #pragma unroll
    for (int a = 0; a < 2; ++a)
        #pragma unroll
        for (int b = 0; b < 8; ++b)
            #pragma unroll
            for (int cc = 0; cc < 4; ++cc) acc[a][b][cc] = 0.f;

    const int nchunks = K >> 5;

    // prologue: load chunk 0
    uint4 pAh0, pAh1, pAl0, pAl1, pWh0, pWh1, pWl0, pWl1;
    {
        const size_t ga = (size_t)(m0 + lr0) * K + lc0;
        const size_t gw = (size_t)(n0 + lr0) * K + lc0;
        pAh0 = *(const uint4*)(Ah + ga);     pAh1 = *(const uint4*)(Ah + ga + 8);
        pAl0 = *(const uint4*)(Al + ga);     pAl1 = *(const uint4*)(Al + ga + 8);
        pWh0 = *(const uint4*)(Wh + gw);     pWh1 = *(const uint4*)(Wh + gw + 8);
        pWl0 = *(const uint4*)(Wl + gw);     pWl1 = *(const uint4*)(Wl + gw + 8);
    }

    for (int c = 0; c < nchunks; ++c) {
        // stage current chunk into smem
        *(uint4*)&sAh[lr0][lc0] = pAh0;  *(uint4*)&sAh[lr0][lc0 + 8] = pAh1;
        *(uint4*)&sAl[lr0][lc0] = pAl0;  *(uint4*)&sAl[lr0][lc0 + 8] = pAl1;
        *(uint4*)&sWh[lr0][lc0] = pWh0;  *(uint4*)&sWh[lr0][lc0 + 8] = pWh1;
        *(uint4*)&sWl[lr0][lc0] = pWl0;  *(uint4*)&sWl[lr0][lc0 + 8] = pWl1;
        __syncthreads();

        // prefetch next chunk to registers
        if (c + 1 < nchunks) {
            const size_t ga = (size_t)(m0 + lr0) * K + (c + 1) * 32 + lc0;
            const size_t gw = (size_t)(n0 + lr0) * K + (c + 1) * 32 + lc0;
            pAh0 = *(const uint4*)(Ah + ga);  pAh1 = *(const uint4*)(Ah + ga + 8);
            pAl0 = *(const uint4*)(Al + ga);  pAl1 = *(const uint4*)(Al + ga + 8);
            pWh0 = *(const uint4*)(Wh + gw);  pWh1 = *(const uint4*)(Wh + gw + 8);
            pWl0 = *(const uint4*)(Wl + gw);  pWl1 = *(const uint4*)(Wl + gw + 8);
        }

        #pragma unroll
        for (int ks = 0; ks < 2; ++ks) {
            const int kc = ks * 16 + tig * 2;
            // A fragments for both m-tiles, both planes
            uint32_t ah[2][4], al[2][4];
            #pragma unroll
            for (int mt = 0; mt < 2; ++mt) {
                const int r = wr * 32 + mt * 16 + g;
                ah[mt][0] = *(const uint32_t*)&sAh[r][kc];
                ah[mt][1] = *(const uint32_t*)&sAh[r + 8][kc];
                ah[mt][2] = *(const uint32_t*)&sAh[r][kc + 8];
                ah[mt][3] = *(const uint32_t*)&sAh[r + 8][kc + 8];
                al[mt][0] = *(const uint32_t*)&sAl[r][kc];
                al[mt][1] = *(const uint32_t*)&sAl[r + 8][kc];
                al[mt][2] = *(const uint32_t*)&sAl[r][kc + 8];
                al[mt][3] = *(const uint32_t*)&sAl[r + 8][kc + 8];
            }
            #pragma unroll
            for (int nt = 0; nt < 8; ++nt) {
                const int wn = wc * 64 + nt * 8 + g;
                uint32_t bh0 = *(const uint32_t*)&sWh[wn][kc];
                uint32_t bh1 = *(const uint32_t*)&sWh[wn][kc + 8];
                uint32_t bl0 = *(const uint32_t*)&sWl[wn][kc];
                uint32_t bl1 = *(const uint32_t*)&sWl[wn][kc + 8];
                #pragma unroll
                for (int mt = 0; mt < 2; ++mt) {
                    mma_bf16(acc[mt][nt], ah[mt][0], ah[mt][1], ah[mt][2], ah[mt][3], bh0, bh1);
                    mma_bf16(acc[mt][nt], ah[mt][0], ah[mt][1], ah[mt][2], ah[mt][3], bl0, bl1);
                    mma_bf16(acc[mt][nt], al[mt][0], al[mt][1], al[mt][2], al[mt][3], bh0, bh1);
                }
            }
        }
        __syncthreads();
    }

    // epilogue: c0,c1 -> (row g, cols 2tig,2tig+1); c2,c3 -> row g+8
    float* Cout = &g_xW[dir][0][0];
    #pragma unroll
    for (int mt = 0; mt < 2; ++mt) {
        const int mrow = m0 + wr * 32 + mt * 16 + g;
        #pragma unroll
        for (int nt = 0; nt < 8; ++nt) {
            const int ncol  = wc * 64 + nt * 8 + tig * 2;   // local
            const int gcol  = n0 + ncol;
            float2 o0 = {acc[mt][nt][0] + sBias[ncol],
                         acc[mt][nt][1] + sBias[ncol + 1]};
            float2 o1 = {acc[mt][nt][2] + sBias[ncol],
                         acc[mt][nt][3] + sBias[ncol + 1]};
            *(float2*)(Cout + (size_t)mrow * G3 + gcol)       = o0;
            *(float2*)(Cout + (size_t)(mrow + 8) * G3 + gcol) = o1;
        }
    }
}

// ---------------- GRU recurrence (R5/R8 structure — best known) ------------
// layer 0 writes bf16 (hi,lo) split for the L1 HMMA projection;
// layer 1 writes fp32 for attention.
__global__ __launch_bounds__(384, 1)
void gru_scan_kernel(const float* __restrict__ whh_f, const float* __restrict__ whh_b,
                     const float* __restrict__ bhh_f, const float* __restrict__ bhh_b,
                     int layer)
{
    const int b   = blockIdx.x >> 1;
    const int dir = blockIdx.x & 1;
    const int j   = threadIdx.x;                 // 0..383 = gate row

    const float* __restrict__ whh = dir ? whh_b : whh_f;
    const float* __restrict__ bhh = dir ? bhh_b : bhh_f;

    __shared__ __align__(16) float h_s[HID];
    __shared__ float rz_s[2 * HID];

    ull w2[64];
    #pragma unroll
    for (int i = 0; i < 64; i += 2) {
        ulonglong2 v = *(const ulonglong2*)(whh + (size_t)j * HID + 2 * i);
        w2[i] = v.x; w2[i + 1] = v.y;
    }
    const bool is_n = (j >= 2 * HID);
    const int  o    = j - 2 * HID;
    const float bj  = is_n ? bhh[j] : 0.f;       // bhh_n stays inside r*(.)
    float hreg = 0.f;
    if (j < HID) h_s[j] = 0.f;

    const float* __restrict__ gi = &g_xW[dir][(size_t)b * TT][0];
    float* __restrict__ zf = &g_z1[(size_t)b * TT][0] + dir * HID;
    __nv_bfloat16* __restrict__ zh = g_z0h + (size_t)b * TT * D2 + dir * HID;
    __nv_bfloat16* __restrict__ zl = g_z0l + (size_t)b * TT * D2 + dir * HID;

    const int t0 = dir ? (TT - 1) : 0;
    float gi_v = __ldcs(gi + (size_t)t0 * G3 + j);
    __syncthreads();

    for (int t = 0; t < TT; ++t) {
        const int tt = dir ? (TT - 1 - t) : t;

        float pre = 0.f;
        if (t + 1 < TT) {
            const int tn = dir ? (TT - 2 - t) : (t + 1);
            pre = __ldcs(gi + (size_t)tn * G3 + j);
        }

        ull a0 = 0ull, a1 = 0ull;
        const ull* h2 = (const ull*)h_s;
        #pragma unroll
        for (int i = 0; i < 64; i += 8) {
            ulonglong2 hv0 = *(const ulonglong2*)(h2 + i);
            ulonglong2 hv1 = *(const ulonglong2*)(h2 + i + 2);
            ulonglong2 hv2 = *(const ulonglong2*)(h2 + i + 4);
            ulonglong2 hv3 = *(const ulonglong2*)(h2 + i + 6);
            a0 = fma2(w2[i],     hv0.x, a0);
            a1 = fma2(w2[i + 1], hv0.y, a1);
            a0 = fma2(w2[i + 2], hv1.x, a0);
            a1 = fma2(w2[i + 3], hv1.y, a1);
            a0 = fma2(w2[i + 4], hv2.x, a0);
            a1 = fma2(w2[i + 5], hv2.y, a1);
            a0 = fma2(w2[i + 6], hv3.x, a0);
            a1 = fma2(w2[i + 7], hv3.y, a1);
        }
        float2 s0 = unpack2(a0), s1 = unpack2(a1);
        float gh = (s0.x + s0.y) + (s1.x + s1.y);

        if (!is_n) rz_s[j] = sigm(gi_v + gh);
        __syncthreads();

        if (is_n) {
            float r  = rz_s[o];
            float zg = rz_s[HID + o];
            float n  = ftanh(gi_v + r * (gh + bj));
            hreg = (1.f - zg) * n + zg * hreg;
            h_s[o] = hreg;
            if (layer) {
                zf[(size_t)tt * D2 + o] = hreg;
            } else {
                __nv_bfloat16 hi = __float2bfloat16(hreg);
                zh[(size_t)tt * D2 + o] = hi;
                zl[(size_t)tt * D2 + o] = __float2bfloat16(hreg - __bfloat162float(hi));
            }
        }
        gi_v = pre;
        __syncthreads();
    }
}

// ---------------- attention pooling + heads --------------------------------
__global__ __launch_bounds__(256)
void attn_head_kernel(const float* __restrict__ attn_w, const float* __restrict__ attn_b,
                      const float* __restrict__ motor_w, const float* __restrict__ motor_b,
                      const float* __restrict__ state_w, const float* __restrict__ state_b,
                      const int* __restrict__ motor_k, float* __restrict__ out)
{
    const int b = blockIdx.x;
    const int tid = threadIdx.x;       // 256 threads
    const int warp = tid >> 5, lane = tid & 31;

    __shared__ float sw[D2];
    __shared__ float sc[TT];
    __shared__ float red[256];
    __shared__ float pooled[D2];

    sw[tid] = attn_w[tid];
    __syncthreads();

    const float* __restrict__ zb = &g_z1[(size_t)b * TT][0];
    const float ab = attn_b[0];

    for (int t = warp; t < TT; t += 8) {
        const float* zt = zb + (size_t)t * D2;
        float s = 0.f;
        #pragma unroll
        for (int d = lane; d < D2; d += 32) s += zt[d] * sw[d];
        #pragma unroll
        for (int o = 16; o; o >>= 1) s += __shfl_xor_sync(0xffffffffu, s, o);
        if (lane == 0) sc[t] = s + ab;
    }
    __syncthreads();

    float m = -INFINITY;
    for (int t = tid; t < TT; t += 256) m = fmaxf(m, sc[t]);
    red[tid] = m; __syncthreads();
    for (int s = 128; s; s >>= 1) {
        if (tid < s) red[tid] = fmaxf(red[tid], red[tid + s]);
        __syncthreads();
    }
    m = red[0]; __syncthreads();

    float sum = 0.f;
    for (int t = tid; t < TT; t += 256) {
        float e = __expf(sc[t] - m);
        sc[t] = e;
        sum += e;
    }
    red[tid] = sum; __syncthreads();
    for (int s = 128; s; s >>= 1) {
        if (tid < s) red[tid] += red[tid + s];
        __syncthreads();
    }
    const float inv = 1.f / red[0];
    __syncthreads();

    float acc = 0.f;
    #pragma unroll 8
    for (int t = 0; t < TT; ++t) acc += sc[t] * zb[(size_t)t * D2 + tid];
    pooled[tid] = acc * inv;
    __syncthreads();

    if (warp < 7) {
        const float* wv;
        float bv;
        int mk = motor_k[b];
        if (warp < 5) { wv = motor_w + warp * D2;              bv = motor_b[warp]; }
        else          { int c = warp - 5;
                        wv = state_w + (size_t)(mk * 2 + c) * D2;
                        bv = state_b[mk * 2 + c]; }
        float s = 0.f;
        #pragma unroll
        for (int d = lane; d < D2; d += 32) s += pooled[d] * wv[d];
        #pragma unroll
        for (int o = 16; o; o >>= 1) s += __shfl_xor_sync(0xffffffffu, s, o);
        if (lane == 0) {
            if (warp < 5) out[b * 5 + warp] = s + bv;
            else          out[BATCH * 5 + b * 2 + (warp - 5)] = s + bv;
        }
    }
}

// ---------------- launch ----------------------------------------------------
extern "C" void kernel_launch(void* const* d_in, const int* in_sizes, int n_in,
                              void* d_out, int out_size)
{
    const float* x        = (const float*)d_in[0];
    const int*   motor_k  = (const int*)  d_in[1];
    const float* wih_l0f  = (const float*)d_in[2];
    const float* whh_l0f  = (const float*)d_in[3];
    const float* bih_l0f  = (const float*)d_in[4];
    const float* bhh_l0f  = (const float*)d_in[5];
    const float* wih_l0b  = (const float*)d_in[6];
    const float* whh_l0b  = (const float*)d_in[7];
    const float* bih_l0b  = (const float*)d_in[8];
    const float* bhh_l0b  = (const float*)d_in[9];
    const float* wih_l1f  = (const float*)d_in[10];
    const float* whh_l1f  = (const float*)d_in[11];
    const float* bih_l1f  = (const float*)d_in[12];
    const float* bhh_l1f  = (const float*)d_in[13];
    const float* wih_l1b  = (const float*)d_in[14];
    const float* whh_l1b  = (const float*)d_in[15];
    const float* bih_l1b  = (const float*)d_in[16];
    const float* bhh_l1b  = (const float*)d_in[17];
    const float* attn_w   = (const float*)d_in[18];
    const float* attn_b   = (const float*)d_in[19];
    const float* motor_w  = (const float*)d_in[20];
    const float* motor_b  = (const float*)d_in[21];
    const float* state_w  = (const float*)d_in[22];
    const float* state_b  = (const float*)d_in[23];
    float* out = (float*)d_out;

    // bf16 (hi,lo) conversions
    convert_kernel<<<2048, 256>>>(x,        0, MROWS * DIN);
    convert_kernel<<<96,   256>>>(wih_l0f,  1, G3 * DIN);
    convert_kernel<<<96,   256>>>(wih_l0b,  2, G3 * DIN);
    convert_kernel<<<384,  256>>>(wih_l1f,  3, G3 * D2);
    convert_kernel<<<384,  256>>>(wih_l1b,  4, G3 * D2);

    dim3 gproj(MROWS / 128, G3 / 128, 2);   // 512 x 3 x 2

    // layer 0
    mma_proj_kernel<<<gproj, 256>>>(bih_l0f, bih_l0b, bhh_l0f, bhh_l0b, DIN, 0);
    gru_scan_kernel<<<BATCH * 2, 384>>>(whh_l0f, whh_l0b, bhh_l0f, bhh_l0b, 0);
    // layer 1
    mma_proj_kernel<<<gproj, 256>>>(bih_l1f, bih_l1b, bhh_l1f, bhh_l1b, D2, 1);
    gru_scan_kernel<<<BATCH * 2, 384>>>(whh_l1f, whh_l1b, bhh_l1f, bhh_l1b, 1);
    // pooling + heads
    attn_head_kernel<<<BATCH, 256>>>(attn_w, attn_b, motor_w, motor_b,
                                     state_w, state_b, motor_k, out);
}